// round 4
// baseline (speedup 1.0000x reference)
#include <cuda_runtime.h>
#include <math.h>

#define NT     224
#define GRID   148
#define RBIG   56
#define XP     108   // X2 pitch in floats (432B = 27*16B; 12 mod 32 banks)
#define HP     132   // H pitch in floats (528B = 33*16B;  4 mod 32 banks)

typedef unsigned long long ull;

#define FMA2(d, a, b, c) \
    asm("fma.rn.f32x2 %0, %1, %2, %3;" : "=l"(d) : "l"(a), "l"(b), "l"(c))
#define ADD2(d, a, b) \
    asm("add.rn.f32x2 %0, %1, %2;" : "=l"(d) : "l"(a), "l"(b))
#define UNPACK2(lo, hi, v) \
    asm("mov.b64 {%0, %1}, %2;" : "=f"(lo), "=f"(hi) : "l"(v))

__device__ __forceinline__ float tanh_fast(float x) {
    float y;
    asm("tanh.approx.f32 %0, %1;" : "=f"(y) : "f"(x));
    return y;
}

// ---------------------------------------------------------------------------
// Activations FIRST: every array below starts at a multiple of 16 bytes from
// the (16B-aligned) dynamic smem base because all preceding sizes are
// multiples of 4 floats. No hand-counted padding.
// ---------------------------------------------------------------------------
struct __align__(16) Smem {
    float X2[RBIG * XP];   // per-row MLP input, duplicated pairs {v,v}
    float H1[RBIG * HP];   // per-row hidden1, duplicated pairs
    float H2[RBIG * HP];   // per-row hidden2, duplicated pairs
    float W1[50 * 64];     // [k][j]
    float W2[64 * 64];     // [k][j]
    float W3[64 * 8];      // [k][j]
    float b1[64], b2[64], b3[8];
};

// ---------------------------------------------------------------------------
// Grey-box CSTR+flash RHS (scaled), matches reference _fg in fp32.
// ---------------------------------------------------------------------------
__device__ __forceinline__ void fg_eval(const float* x, float u0f, float u1f,
                                        float* g) {
    const float Hr  = 0.3f * x[0] + 0.7f;
    const float CAr = 0.2f * x[1] + 0.5f;
    const float CBr = 0.2f * x[2] + 0.5f;
    const float Tr  = 5.0f * x[3] + 310.0f;
    const float Hb  = 0.3f * x[4] + 0.7f;
    const float CAb = 0.2f * x[5] + 0.5f;
    const float CBb = 0.2f * x[6] + 0.5f;
    const float Tb  = 5.0f * x[7] + 310.0f;
    const float Fu  = 0.1f  * u0f + 1.0f;
    const float Du  = 0.05f * u1f + 0.5f;

    const float den = 3.5f * CAb + 1.1f * CBb;
    const float CAd = 3.5f * CAb / den;
    const float CBd = 1.1f * CBb / den;
    const float Fr  = sqrtf(Hr);
    const float Fb  = sqrtf(Hb);
    const float k1c = 20000.0f * expf(-3000.0f / Tr);
    const float r1  = k1c * CAr;
    const float rHr = 1.0f / Hr;
    const float rHb = 1.0f / Hb;

    const float dHr  = Fu + Du - Fr;
    const float dCAr = (Fu * (1.0f - CAr) + Du * (CAd - CAr)) * rHr - r1;
    const float dCBr = (-Fu * CBr + Du * (CBd - CBr)) * rHr + r1;
    const float dTr  = (Fu * (320.0f - Tr) + Du * (310.0f - Tr)) * rHr
                     - (200.0f / 15.0f) * rHr + r1 * (10.0f / 15.0f);
    const float dHb  = Fr - Fb - Du;
    const float dCAb = (Fr * (CAr - CAb) + Du * (CAb - CAd)) * rHb;
    const float dCBb = (Fr * (CBr - CBb) + Du * (CBb - CBd)) * rHb;
    const float dTb  = Fr * (Tr - Tb) * rHb + (200.0f / 15.0f) * rHb;

    g[0] = dHr  * (1.0f / 0.3f);
    g[1] = dCAr * (1.0f / 0.2f);
    g[2] = dCBr * (1.0f / 0.2f);
    g[3] = dTr  * (1.0f / 5.0f);
    g[4] = dHb  * (1.0f / 0.3f);
    g[5] = dCAb * (1.0f / 0.2f);
    g[6] = dCBb * (1.0f / 0.2f);
    g[7] = dTb  * (1.0f / 5.0f);
}

// ---------------------------------------------------------------------------
// Persistent kernel. 4 lanes per row (same warp). No __syncthreads in loop.
// Lane ts computes output columns [16ts, 16ts+16) of each dense layer.
// Activations live in smem as {v,v} pairs; weights read as warp broadcasts.
// ---------------------------------------------------------------------------
__global__ void __launch_bounds__(NT, 1)
cstr_flash_kernel(const float* __restrict__ useq, const float* __restrict__ xGz0,
                  const float* __restrict__ gW1, const float* __restrict__ gb1,
                  const float* __restrict__ gW2, const float* __restrict__ gb2,
                  const float* __restrict__ gW3, const float* __restrict__ gb3,
                  float* __restrict__ out, int T, int rbig, int nbig) {
    extern __shared__ char smem_raw[];
    Smem& S = *reinterpret_cast<Smem*>(smem_raw);

    const int tid = threadIdx.x;
    const int b   = blockIdx.x;

    // weights
    for (int i = tid; i < 50 * 64; i += NT) S.W1[i] = gW1[i];
    for (int i = tid; i < 64 * 64; i += NT) S.W2[i] = gW2[i];
    for (int i = tid; i < 64 * 8;  i += NT) S.W3[i] = gW3[i];
    if (tid < 64) { S.b1[tid] = gb1[tid]; S.b2[tid] = gb2[tid]; }
    if (tid < 8)  { S.b3[tid] = gb3[tid]; }

    const int r  = tid >> 2;          // local row 0..55
    const int ts = tid & 3;           // j-slice
    const int nrows    = (b < nbig) ? rbig : (rbig - 8);
    const long rowstart = (b < nbig) ? (long)b * rbig
                                     : (long)nbig * rbig + (long)(b - nbig) * (rbig - 8);
    const bool active = (r < nrows);
    const long gr = rowstart + r;

    float* xrow  = S.X2 + r * XP;
    float* h1row = S.H1 + r * HP;
    float* h2row = S.H2 + r * HP;
    const float* w1c = S.W1 + 16 * ts;
    const float* w2c = S.W2 + 16 * ts;

    float xG[8], xcur[8], kacc[8], yp[32];
    float u0 = 0.f, u1 = 0.f;
#pragma unroll
    for (int c = 0; c < 8; c++) { xG[c] = 0.f; xcur[c] = 0.f; kacc[c] = 0.f; }
#pragma unroll
    for (int j = 0; j < 32; j++) yp[j] = 0.f;

    if (ts == 0 && active) {
        const float* x0 = xGz0 + gr * 48;
#pragma unroll
        for (int c = 0; c < 8; c++) xG[c] = x0[c];
#pragma unroll
        for (int j = 0; j < 32; j++) yp[j] = x0[8 + j];
        for (int v = 0; v < 48; v++) {          // dup X2 k=0..47
            const float f = x0[v];
            xrow[2 * v] = f; xrow[2 * v + 1] = f;
        }
        u0 = useq[gr * T * 2 + 0];
        u1 = useq[gr * T * 2 + 1];
        xrow[96] = u0; xrow[97] = u0; xrow[98] = u1; xrow[99] = u1;
        xrow[100] = 0.f; xrow[101] = 0.f; xrow[102] = 0.f; xrow[103] = 0.f;
        float* op = out + gr * T * 8;           // y_0 = xG_0
        *(float4*)(op)     = make_float4(xG[0], xG[1], xG[2], xG[3]);
        *(float4*)(op + 4) = make_float4(xG[4], xG[5], xG[6], xG[7]);
    }
    __syncthreads();

#pragma unroll 1
    for (int t = 0; t < T; t++) {
#pragma unroll 1
        for (int s = 0; s < 4; s++) {
            // ---------------- layer 1: 50 -> 64, tanh ----------------
            ull a[8];
#pragma unroll
            for (int p = 0; p < 8; p++)
                a[p] = *(const ull*)(S.b1 + 16 * ts + 2 * p);
#pragma unroll 10
            for (int k = 0; k < 50; k++) {
                const ull xv = *(const ull*)(xrow + 2 * k);
                const float* w = w1c + k * 64;
                const ulonglong2 wa = *(const ulonglong2*)(w);
                const ulonglong2 wb = *(const ulonglong2*)(w + 4);
                const ulonglong2 wc = *(const ulonglong2*)(w + 8);
                const ulonglong2 wd = *(const ulonglong2*)(w + 12);
                FMA2(a[0], xv, wa.x, a[0]);
                FMA2(a[1], xv, wa.y, a[1]);
                FMA2(a[2], xv, wb.x, a[2]);
                FMA2(a[3], xv, wb.y, a[3]);
                FMA2(a[4], xv, wc.x, a[4]);
                FMA2(a[5], xv, wc.y, a[5]);
                FMA2(a[6], xv, wd.x, a[6]);
                FMA2(a[7], xv, wd.y, a[7]);
            }
#pragma unroll
            for (int p = 0; p < 8; p++) {
                float f0, f1;
                UNPACK2(f0, f1, a[p]);
                const float t0 = tanh_fast(f0), t1 = tanh_fast(f1);
                *(float4*)(h1row + 32 * ts + 4 * p) = make_float4(t0, t0, t1, t1);
            }
            __syncwarp();

            // ---------------- layer 2: 64 -> 64, tanh ----------------
#pragma unroll
            for (int p = 0; p < 8; p++)
                a[p] = *(const ull*)(S.b2 + 16 * ts + 2 * p);
#pragma unroll 8
            for (int k = 0; k < 64; k++) {
                const ull xv = *(const ull*)(h1row + 2 * k);
                const float* w = w2c + k * 64;
                const ulonglong2 wa = *(const ulonglong2*)(w);
                const ulonglong2 wb = *(const ulonglong2*)(w + 4);
                const ulonglong2 wc = *(const ulonglong2*)(w + 8);
                const ulonglong2 wd = *(const ulonglong2*)(w + 12);
                FMA2(a[0], xv, wa.x, a[0]);
                FMA2(a[1], xv, wa.y, a[1]);
                FMA2(a[2], xv, wb.x, a[2]);
                FMA2(a[3], xv, wb.y, a[3]);
                FMA2(a[4], xv, wc.x, a[4]);
                FMA2(a[5], xv, wc.y, a[5]);
                FMA2(a[6], xv, wd.x, a[6]);
                FMA2(a[7], xv, wd.y, a[7]);
            }
#pragma unroll
            for (int p = 0; p < 8; p++) {
                float f0, f1;
                UNPACK2(f0, f1, a[p]);
                const float t0 = tanh_fast(f0), t1 = tanh_fast(f1);
                *(float4*)(h2row + 32 * ts + 4 * p) = make_float4(t0, t0, t1, t1);
            }
            __syncwarp();

            // ---------------- layer 3: 64 -> 8 (k-split 4 + shfl) ----------------
            ull c4[4];
            c4[0] = 0ull; c4[1] = 0ull; c4[2] = 0ull; c4[3] = 0ull;
#pragma unroll
            for (int i = 0; i < 16; i++) {
                const ull xv = *(const ull*)(h2row + 32 * ts + 2 * i);
                const float* w = S.W3 + 8 * (16 * ts + i);
                const ulonglong2 wa = *(const ulonglong2*)(w);
                const ulonglong2 wb = *(const ulonglong2*)(w + 4);
                FMA2(c4[0], xv, wa.x, c4[0]);
                FMA2(c4[1], xv, wa.y, c4[1]);
                FMA2(c4[2], xv, wb.x, c4[2]);
                FMA2(c4[3], xv, wb.y, c4[3]);
            }
#pragma unroll
            for (int m = 1; m <= 2; m <<= 1) {
#pragma unroll
                for (int j = 0; j < 4; j++) {
                    const ull o = __shfl_xor_sync(0xffffffffu, c4[j], m);
                    ADD2(c4[j], c4[j], o);
                }
            }

            // ---------------- owner epilogue ----------------
            if (ts == 0) {
                float fnn[8];
                UNPACK2(fnn[0], fnn[1], c4[0]);
                UNPACK2(fnn[2], fnn[3], c4[1]);
                UNPACK2(fnn[4], fnn[5], c4[2]);
                UNPACK2(fnn[6], fnn[7], c4[3]);
#pragma unroll
                for (int c = 0; c < 8; c++) fnn[c] += S.b3[c];

                float g[8];
                fg_eval((s == 0) ? xG : xcur, u0, u1, g);
                float kv[8];
#pragma unroll
                for (int c = 0; c < 8; c++) kv[c] = g[c] + fnn[c];

                if (s == 0) {
#pragma unroll
                    for (int c = 0; c < 8; c++) {
                        kacc[c] = kv[c];
                        xcur[c] = xG[c] + 0.005f * kv[c];
                    }
                    // zi -> X2 k=8..39 (dup floats 16..79)
#pragma unroll
                    for (int m = 0; m < 4; m++) {
#pragma unroll
                        for (int c = 0; c < 8; c += 2) {
                            const float a0 = yp[8 * m + c];
                            const float a1 = yp[8 * m + c + 1];
                            const float n0 = (m < 3) ? yp[8 * (m + 1) + c]     : xG[c];
                            const float n1 = (m < 3) ? yp[8 * (m + 1) + c + 1] : xG[c + 1];
                            const float z0 = 0.5f * (a0 + n0);
                            const float z1 = 0.5f * (a1 + n1);
                            *(float4*)(xrow + 16 + 2 * (8 * m + c)) =
                                make_float4(z0, z0, z1, z1);
                        }
                    }
                } else if (s == 1) {
#pragma unroll
                    for (int c = 0; c < 8; c++) {
                        kacc[c] += 2.0f * kv[c];
                        xcur[c] = xG[c] + 0.005f * kv[c];
                    }
                } else if (s == 2) {
#pragma unroll
                    for (int c = 0; c < 8; c++) {
                        kacc[c] += 2.0f * kv[c];
                        xcur[c] = xG[c] + 0.01f * kv[c];
                    }
                    // zs = [yp[8:32], xG] -> X2 k=8..39
#pragma unroll
                    for (int q = 0; q < 32; q += 2) {
                        const float z0 = (q < 24)     ? yp[8 + q]     : xG[q - 24];
                        const float z1 = (q + 1 < 24) ? yp[8 + q + 1] : xG[q + 1 - 24];
                        *(float4*)(xrow + 16 + 2 * q) = make_float4(z0, z0, z1, z1);
                    }
                } else {
#pragma unroll
                    for (int c = 0; c < 8; c++) kacc[c] += kv[c];
                    float xnew[8];
#pragma unroll
                    for (int c = 0; c < 8; c++)
                        xnew[c] = xG[c] + (0.01f / 6.0f) * kacc[c];
                    // yp <- [yp[8:], xG_old]
#pragma unroll
                    for (int j = 0; j < 24; j++) yp[j] = yp[j + 8];
#pragma unroll
                    for (int c = 0; c < 8; c++) yp[24 + c] = xG[c];
                    // upseq shift (X2 floats 80..95), append u
#pragma unroll
                    for (int q = 0; q < 6; q++) {
                        xrow[80 + 2 * q]     = xrow[84 + 2 * q];
                        xrow[80 + 2 * q + 1] = xrow[85 + 2 * q];
                    }
                    xrow[92] = u0; xrow[93] = u0; xrow[94] = u1; xrow[95] = u1;
#pragma unroll
                    for (int c = 0; c < 8; c++) xG[c] = xnew[c];
                    if (active && t + 1 < T) {
                        u0 = useq[(gr * T + t + 1) * 2 + 0];
                        u1 = useq[(gr * T + t + 1) * 2 + 1];
                        float* op = out + (gr * T + t + 1) * 8;
                        *(float4*)(op)     = make_float4(xG[0], xG[1], xG[2], xG[3]);
                        *(float4*)(op + 4) = make_float4(xG[4], xG[5], xG[6], xG[7]);
                    }
                    xrow[96] = u0; xrow[97] = u0; xrow[98] = u1; xrow[99] = u1;
                }
                // x substep input -> X2 k=0..7 (dup floats 0..15)
                const float* xw = (s == 3) ? xG : xcur;
#pragma unroll
                for (int c = 0; c < 8; c += 2) {
                    *(float4*)(xrow + 2 * c) =
                        make_float4(xw[c], xw[c], xw[c + 1], xw[c + 1]);
                }
            }
            __syncwarp();
        }
    }
}

// ---------------------------------------------------------------------------
extern "C" void kernel_launch(void* const* d_in, const int* in_sizes, int n_in,
                              void* d_out, int out_size) {
    const float* useq = (const float*)d_in[0];
    const float* xGz0 = (const float*)d_in[1];
    const float* W1   = (const float*)d_in[2];
    const float* b1   = (const float*)d_in[3];
    const float* W2   = (const float*)d_in[4];
    const float* b2   = (const float*)d_in[5];
    const float* W3   = (const float*)d_in[6];
    const float* b3   = (const float*)d_in[7];
    float* out = (float*)d_out;

    const int B = in_sizes[1] / 48;
    const int T = in_sizes[0] / (B * 2);

    // Balanced split: nbig CTAs of rbig rows, rest rbig-8 (B=8192 -> 56/48).
    int rbig = ((B + GRID - 1) / GRID + 7) & ~7;
    if (rbig < 8) rbig = 8;
    int nbig = (B - GRID * (rbig - 8)) / 8;
    if (nbig < 0) nbig = 0;
    if (nbig > GRID) nbig = GRID;

    const int smem = (int)sizeof(Smem);
    cudaFuncSetAttribute(cstr_flash_kernel,
                         cudaFuncAttributeMaxDynamicSharedMemorySize, smem);
    cstr_flash_kernel<<<GRID, NT, smem>>>(useq, xGz0, W1, b1, W2, b2, W3, b3,
                                          out, T, rbig, nbig);
}

// round 5
// speedup vs baseline: 2.4778x; 2.4778x over previous
#include <cuda_runtime.h>
#include <math.h>

#define NT   128
#define BC   64
#define XP   104   // X2 pitch (dup floats): 104*4B = 26*16B; 104 mod 32 = 8
#define HP   132   // H pitch  (dup floats): 132*4B = 33*16B; 132 mod 32 = 4

typedef unsigned long long ull;

#define FMA2(d, a, b, c) \
    asm("fma.rn.f32x2 %0, %1, %2, %3;" : "=l"(d) : "l"(a), "l"(b), "l"(c))
#define ADD2(d, a, b) \
    asm("add.rn.f32x2 %0, %1, %2;" : "=l"(d) : "l"(a), "l"(b))
#define UNPACK2(lo, hi, v) \
    asm("mov.b64 {%0, %1}, %2;" : "=f"(lo), "=f"(hi) : "l"(v))

__device__ __forceinline__ float tanh_fast(float x) {
    float y;
    asm("tanh.approx.f32 %0, %1;" : "=f"(y) : "f"(x));
    return y;
}

// ---------------------------------------------------------------------------
// All array sizes are multiples of 4 floats -> every member 16B aligned.
// ---------------------------------------------------------------------------
struct __align__(16) Smem {
    float X2[BC * XP];   // MLP input per row, duplicated pairs {v,v}
    float H1[BC * HP];   // hidden1, duplicated pairs
    float H2[BC * HP];   // hidden2, duplicated pairs
    float W1[50 * 64];   // [k][j]
    float W2[64 * 64];   // [k][j]
    float W3[64 * 8];    // [k][j]
    float b1[64], b2[64], b3[8];
};

// ---------------------------------------------------------------------------
// Grey-box CSTR+flash RHS (scaled), matches reference _fg in fp32.
// ---------------------------------------------------------------------------
__device__ __forceinline__ void fg_eval(const float* x, float u0f, float u1f,
                                        float* g) {
    const float Hr  = 0.3f * x[0] + 0.7f;
    const float CAr = 0.2f * x[1] + 0.5f;
    const float CBr = 0.2f * x[2] + 0.5f;
    const float Tr  = 5.0f * x[3] + 310.0f;
    const float Hb  = 0.3f * x[4] + 0.7f;
    const float CAb = 0.2f * x[5] + 0.5f;
    const float CBb = 0.2f * x[6] + 0.5f;
    const float Tb  = 5.0f * x[7] + 310.0f;
    const float Fu  = 0.1f  * u0f + 1.0f;
    const float Du  = 0.05f * u1f + 0.5f;

    const float den = 3.5f * CAb + 1.1f * CBb;
    const float CAd = 3.5f * CAb / den;
    const float CBd = 1.1f * CBb / den;
    const float Fr  = sqrtf(Hr);
    const float Fb  = sqrtf(Hb);
    const float k1c = 20000.0f * expf(-3000.0f / Tr);
    const float r1  = k1c * CAr;
    const float rHr = 1.0f / Hr;
    const float rHb = 1.0f / Hb;

    const float dHr  = Fu + Du - Fr;
    const float dCAr = (Fu * (1.0f - CAr) + Du * (CAd - CAr)) * rHr - r1;
    const float dCBr = (-Fu * CBr + Du * (CBd - CBr)) * rHr + r1;
    const float dTr  = (Fu * (320.0f - Tr) + Du * (310.0f - Tr)) * rHr
                     - (200.0f / 15.0f) * rHr + r1 * (10.0f / 15.0f);
    const float dHb  = Fr - Fb - Du;
    const float dCAb = (Fr * (CAr - CAb) + Du * (CAb - CAd)) * rHb;
    const float dCBb = (Fr * (CBr - CBb) + Du * (CBb - CBd)) * rHb;
    const float dTb  = Fr * (Tr - Tb) * rHb + (200.0f / 15.0f) * rHb;

    g[0] = dHr  * (1.0f / 0.3f);
    g[1] = dCAr * (1.0f / 0.2f);
    g[2] = dCBr * (1.0f / 0.2f);
    g[3] = dTr  * (1.0f / 5.0f);
    g[4] = dHb  * (1.0f / 0.3f);
    g[5] = dCAb * (1.0f / 0.2f);
    g[6] = dCBb * (1.0f / 0.2f);
    g[7] = dTb  * (1.0f / 5.0f);
}

// ---------------------------------------------------------------------------
// Dense layer, tanh, 4 rows x 8 cols per thread (cols {4cg..+3} and {32+4cg..+3}).
// X/Y hold duplicated {v,v} pairs. 1 wavefront per LDS.128 by construction.
// ---------------------------------------------------------------------------
template <int KP, int LDX, int LDY>
__device__ __forceinline__ void dense_tanh(const float* __restrict__ Xr0,
                                           const float* __restrict__ W,
                                           const float* __restrict__ bias,
                                           float* __restrict__ Yr0, int cg) {
    ull acc[4][4];
    const ull bA0 = *(const ull*)(bias + 4 * cg);
    const ull bA1 = *(const ull*)(bias + 4 * cg + 2);
    const ull bB0 = *(const ull*)(bias + 32 + 4 * cg);
    const ull bB1 = *(const ull*)(bias + 32 + 4 * cg + 2);
#pragma unroll
    for (int i = 0; i < 4; i++) {
        acc[i][0] = bA0; acc[i][1] = bA1; acc[i][2] = bB0; acc[i][3] = bB1;
    }
    const float* wA = W + 4 * cg;
    const float* wB = W + 32 + 4 * cg;
#pragma unroll
    for (int kp = 0; kp < KP; kp++) {
        const ulonglong2 wA0 = *(const ulonglong2*)(wA + (2 * kp) * 64);
        const ulonglong2 wB0 = *(const ulonglong2*)(wB + (2 * kp) * 64);
        const ulonglong2 wA1 = *(const ulonglong2*)(wA + (2 * kp + 1) * 64);
        const ulonglong2 wB1 = *(const ulonglong2*)(wB + (2 * kp + 1) * 64);
#pragma unroll
        for (int i = 0; i < 4; i++) {
            const ulonglong2 xv = *(const ulonglong2*)(Xr0 + i * LDX + 4 * kp);
            FMA2(acc[i][0], xv.x, wA0.x, acc[i][0]);
            FMA2(acc[i][1], xv.x, wA0.y, acc[i][1]);
            FMA2(acc[i][2], xv.x, wB0.x, acc[i][2]);
            FMA2(acc[i][3], xv.x, wB0.y, acc[i][3]);
            FMA2(acc[i][0], xv.y, wA1.x, acc[i][0]);
            FMA2(acc[i][1], xv.y, wA1.y, acc[i][1]);
            FMA2(acc[i][2], xv.y, wB1.x, acc[i][2]);
            FMA2(acc[i][3], xv.y, wB1.y, acc[i][3]);
        }
    }
#pragma unroll
    for (int i = 0; i < 4; i++) {
        float f0, f1, f2, f3;
        float* y = Yr0 + i * LDY;
        UNPACK2(f0, f1, acc[i][0]);
        UNPACK2(f2, f3, acc[i][1]);
        {
            const float t0 = tanh_fast(f0), t1 = tanh_fast(f1);
            const float t2 = tanh_fast(f2), t3 = tanh_fast(f3);
            *(float4*)(y + 8 * cg)     = make_float4(t0, t0, t1, t1);
            *(float4*)(y + 8 * cg + 4) = make_float4(t2, t2, t3, t3);
        }
        UNPACK2(f0, f1, acc[i][2]);
        UNPACK2(f2, f3, acc[i][3]);
        {
            const float t0 = tanh_fast(f0), t1 = tanh_fast(f1);
            const float t2 = tanh_fast(f2), t3 = tanh_fast(f3);
            *(float4*)(y + 64 + 8 * cg)     = make_float4(t0, t0, t1, t1);
            *(float4*)(y + 64 + 8 * cg + 4) = make_float4(t2, t2, t3, t3);
        }
    }
}

// ---------------------------------------------------------------------------
// Persistent kernel: CTA = 64 rows, 4 warps; warp w owns rows [16w,16w+16).
// Main loop uses only __syncwarp. Lanes cg<4 of each 8-lane group own one
// row's RK4 state in registers.
// ---------------------------------------------------------------------------
__global__ void __launch_bounds__(NT, 1)
cstr_flash_kernel(const float* __restrict__ useq, const float* __restrict__ xGz0,
                  const float* __restrict__ gW1, const float* __restrict__ gb1,
                  const float* __restrict__ gW2, const float* __restrict__ gb2,
                  const float* __restrict__ gW3, const float* __restrict__ gb3,
                  float* __restrict__ out, int T) {
    extern __shared__ char smem_raw[];
    Smem& S = *reinterpret_cast<Smem*>(smem_raw);

    const int tid = threadIdx.x;
    const int cg  = tid & 7;     // column group
    const int rgl = tid >> 3;    // row group 0..15 (4 rows each)

    // weights
    for (int i = tid; i < 50 * 64; i += NT) S.W1[i] = gW1[i];
    for (int i = tid; i < 64 * 64; i += NT) S.W2[i] = gW2[i];
    for (int i = tid; i < 64 * 8;  i += NT) S.W3[i] = gW3[i];
    if (tid < 64) { S.b1[tid] = gb1[tid]; S.b2[tid] = gb2[tid]; }
    if (tid < 8)  { S.b3[tid] = gb3[tid]; }

    const int  r    = rgl * 4 + cg;          // owned row (valid if cg < 4)
    const bool own  = (cg < 4);
    const long gr   = (long)blockIdx.x * BC + r;
    float* xrow = S.X2 + r * XP;

    const float* Xt0 = S.X2 + (rgl * 4) * XP;  // thread-tile row 0
    float*       H1t = S.H1 + (rgl * 4) * HP;
    float*       H2t = S.H2 + (rgl * 4) * HP;

    float xG[8], xcur[8], kacc[8], yp[32];
    float u0 = 0.f, u1 = 0.f;
#pragma unroll
    for (int c = 0; c < 8; c++) { xG[c] = 0.f; xcur[c] = 0.f; kacc[c] = 0.f; }
#pragma unroll
    for (int j = 0; j < 32; j++) yp[j] = 0.f;

    if (own) {
        const float* x0 = xGz0 + gr * 48;
#pragma unroll
        for (int c = 0; c < 8; c++) xG[c] = x0[c];
#pragma unroll
        for (int j = 0; j < 32; j++) yp[j] = x0[8 + j];
        for (int v = 0; v < 48; v += 2) {
            const float f0 = x0[v], f1 = x0[v + 1];
            *(float4*)(xrow + 2 * v) = make_float4(f0, f0, f1, f1);
        }
        u0 = useq[gr * T * 2 + 0];
        u1 = useq[gr * T * 2 + 1];
        *(float4*)(xrow + 96)  = make_float4(u0, u0, u1, u1);
        *(float4*)(xrow + 100) = make_float4(0.f, 0.f, 0.f, 0.f);
        float* op = out + gr * T * 8;
        *(float4*)(op)     = make_float4(xG[0], xG[1], xG[2], xG[3]);
        *(float4*)(op + 4) = make_float4(xG[4], xG[5], xG[6], xG[7]);
    }
    __syncthreads();

#pragma unroll 1
    for (int t = 0; t < T; t++) {
#pragma unroll 1
        for (int s = 0; s < 4; s++) {
            dense_tanh<25, XP, HP>(Xt0, S.W1, S.b1, H1t, cg);
            __syncwarp();
            dense_tanh<32, HP, HP>(H1t, S.W2, S.b2, H2t, cg);
            __syncwarp();

            // ---- layer 3: 64 -> 8, k-slice [8cg, 8cg+8) ----
            ull c4[4][4];
#pragma unroll
            for (int i = 0; i < 4; i++)
#pragma unroll
                for (int p = 0; p < 4; p++) c4[i][p] = 0ull;
#pragma unroll
            for (int kk = 0; kk < 4; kk++) {
                const float* w = S.W3 + (8 * cg + 2 * kk) * 8;
                const ulonglong2 wa0 = *(const ulonglong2*)(w);
                const ulonglong2 wb0 = *(const ulonglong2*)(w + 4);
                const ulonglong2 wa1 = *(const ulonglong2*)(w + 8);
                const ulonglong2 wb1 = *(const ulonglong2*)(w + 12);
#pragma unroll
                for (int i = 0; i < 4; i++) {
                    const ulonglong2 xv =
                        *(const ulonglong2*)(H2t + i * HP + 16 * cg + 4 * kk);
                    FMA2(c4[i][0], xv.x, wa0.x, c4[i][0]);
                    FMA2(c4[i][1], xv.x, wa0.y, c4[i][1]);
                    FMA2(c4[i][2], xv.x, wb0.x, c4[i][2]);
                    FMA2(c4[i][3], xv.x, wb0.y, c4[i][3]);
                    FMA2(c4[i][0], xv.y, wa1.x, c4[i][0]);
                    FMA2(c4[i][1], xv.y, wa1.y, c4[i][1]);
                    FMA2(c4[i][2], xv.y, wb1.x, c4[i][2]);
                    FMA2(c4[i][3], xv.y, wb1.y, c4[i][3]);
                }
            }
            // butterfly across the 8 cg lanes
#pragma unroll
            for (int m = 1; m <= 4; m <<= 1) {
#pragma unroll
                for (int i = 0; i < 4; i++)
#pragma unroll
                    for (int p = 0; p < 4; p++) {
                        const ull o = __shfl_xor_sync(0xffffffffu, c4[i][p], m);
                        ADD2(c4[i][p], c4[i][p], o);
                    }
            }

            // select own row's result without runtime array indexing
            ull m0 = c4[3][0], m1 = c4[3][1], m2 = c4[3][2], m3 = c4[3][3];
            if (cg == 0) { m0 = c4[0][0]; m1 = c4[0][1]; m2 = c4[0][2]; m3 = c4[0][3]; }
            if (cg == 1) { m0 = c4[1][0]; m1 = c4[1][1]; m2 = c4[1][2]; m3 = c4[1][3]; }
            if (cg == 2) { m0 = c4[2][0]; m1 = c4[2][1]; m2 = c4[2][2]; m3 = c4[2][3]; }

            // ---- owner epilogue (lanes cg<4, one row each) ----
            if (own) {
                float fnn[8];
                UNPACK2(fnn[0], fnn[1], m0);
                UNPACK2(fnn[2], fnn[3], m1);
                UNPACK2(fnn[4], fnn[5], m2);
                UNPACK2(fnn[6], fnn[7], m3);
#pragma unroll
                for (int c = 0; c < 8; c++) fnn[c] += S.b3[c];

                float g[8];
                fg_eval((s == 0) ? xG : xcur, u0, u1, g);
                float kv[8];
#pragma unroll
                for (int c = 0; c < 8; c++) kv[c] = g[c] + fnn[c];

                if (s == 0) {
#pragma unroll
                    for (int c = 0; c < 8; c++) {
                        kacc[c] = kv[c];
                        xcur[c] = xG[c] + 0.005f * kv[c];
                    }
                    // zi -> X2 k=8..39 (dup floats 16..79)
#pragma unroll
                    for (int m = 0; m < 4; m++) {
#pragma unroll
                        for (int c = 0; c < 8; c += 2) {
                            const float a0 = yp[8 * m + c];
                            const float a1 = yp[8 * m + c + 1];
                            const float n0 = (m < 3) ? yp[8 * (m + 1) + c]     : xG[c];
                            const float n1 = (m < 3) ? yp[8 * (m + 1) + c + 1] : xG[c + 1];
                            const float z0 = 0.5f * (a0 + n0);
                            const float z1 = 0.5f * (a1 + n1);
                            *(float4*)(xrow + 16 + 2 * (8 * m + c)) =
                                make_float4(z0, z0, z1, z1);
                        }
                    }
                } else if (s == 1) {
#pragma unroll
                    for (int c = 0; c < 8; c++) {
                        kacc[c] += 2.0f * kv[c];
                        xcur[c] = xG[c] + 0.005f * kv[c];
                    }
                } else if (s == 2) {
#pragma unroll
                    for (int c = 0; c < 8; c++) {
                        kacc[c] += 2.0f * kv[c];
                        xcur[c] = xG[c] + 0.01f * kv[c];
                    }
                    // zs = [yp[8:32], xG] -> X2 k=8..39
#pragma unroll
                    for (int q = 0; q < 32; q += 2) {
                        const float z0 = (q < 24)     ? yp[8 + q]     : xG[q - 24];
                        const float z1 = (q + 1 < 24) ? yp[8 + q + 1] : xG[q + 1 - 24];
                        *(float4*)(xrow + 16 + 2 * q) = make_float4(z0, z0, z1, z1);
                    }
                } else {
#pragma unroll
                    for (int c = 0; c < 8; c++) kacc[c] += kv[c];
                    float xnew[8];
#pragma unroll
                    for (int c = 0; c < 8; c++)
                        xnew[c] = xG[c] + (0.01f / 6.0f) * kacc[c];
                    // yp <- [yp[8:], xG_old]
#pragma unroll
                    for (int j = 0; j < 24; j++) yp[j] = yp[j + 8];
#pragma unroll
                    for (int c = 0; c < 8; c++) yp[24 + c] = xG[c];
                    // upseq shift (dup floats 80..95), append u
#pragma unroll
                    for (int q = 0; q < 6; q++) {
                        xrow[80 + 2 * q]     = xrow[84 + 2 * q];
                        xrow[80 + 2 * q + 1] = xrow[85 + 2 * q];
                    }
                    xrow[92] = u0; xrow[93] = u0; xrow[94] = u1; xrow[95] = u1;
#pragma unroll
                    for (int c = 0; c < 8; c++) xG[c] = xnew[c];
                    if (t + 1 < T) {
                        u0 = useq[(gr * T + t + 1) * 2 + 0];
                        u1 = useq[(gr * T + t + 1) * 2 + 1];
                        float* op = out + (gr * T + t + 1) * 8;
                        *(float4*)(op)     = make_float4(xG[0], xG[1], xG[2], xG[3]);
                        *(float4*)(op + 4) = make_float4(xG[4], xG[5], xG[6], xG[7]);
                    }
                    *(float4*)(xrow + 96) = make_float4(u0, u0, u1, u1);
                }
                // substep x -> X2 k=0..7 (dup floats 0..15)
                const float* xw = (s == 3) ? xG : xcur;
#pragma unroll
                for (int c = 0; c < 8; c += 2) {
                    *(float4*)(xrow + 2 * c) =
                        make_float4(xw[c], xw[c], xw[c + 1], xw[c + 1]);
                }
            }
            __syncwarp();
        }
    }
}

// ---------------------------------------------------------------------------
extern "C" void kernel_launch(void* const* d_in, const int* in_sizes, int n_in,
                              void* d_out, int out_size) {
    const float* useq = (const float*)d_in[0];
    const float* xGz0 = (const float*)d_in[1];
    const float* W1   = (const float*)d_in[2];
    const float* b1   = (const float*)d_in[3];
    const float* W2   = (const float*)d_in[4];
    const float* b2   = (const float*)d_in[5];
    const float* W3   = (const float*)d_in[6];
    const float* b3   = (const float*)d_in[7];
    float* out = (float*)d_out;

    const int B = in_sizes[1] / 48;
    const int T = in_sizes[0] / (B * 2);

    const int smem = (int)sizeof(Smem);
    cudaFuncSetAttribute(cstr_flash_kernel,
                         cudaFuncAttributeMaxDynamicSharedMemorySize, smem);
    cstr_flash_kernel<<<B / BC, NT, smem>>>(useq, xGz0, W1, b1, W2, b2, W3, b3,
                                            out, T);
}